// round 11
// baseline (speedup 1.0000x reference)
#include <cuda_runtime.h>
#include <stdint.h>

// out[b,c, pr*64+i, pc*64+j] = x[b,c, qr*64+i, qc*64+j] + pos[c*64+q]
//   p = pr*8+pc, q = (p+c) & 63
// B=8, C=64, H=W=512. 1 GiB HBM traffic; pure streaming permutation.
//
// FINAL (R7, confirmed over 3 runs: 156.4/156.4/156.1 us):
//  - 1024-thread CTAs, 4096 one-shot blocks (HW work-steal; persistent
//    grid regressed to 176us by defeating rebalancing)
//  - 256-bit global accesses (ld/st.global.v8.f32, sm_100+)
//  - ILP=4 front-batched loads: 128B in flight/thread is the RF sweet spot
//    (ILP=8 at v8 hit the 64-reg cap, serialized loads, 180us)
//  - streaming cache hints (.cs) — zero-reuse stream
// ncu: 149.7us, DRAM 85.9% (6.80 TB/s) — the path-independent balanced
// read/write stream ceiling on GB300, reproduced across 4 configs.
// Traffic (512MiB in + 512MiB out, no reuse) is irreducible.

#define ILP 4
#define TPB 1024u

__device__ __forceinline__ void ldg_v8_cs(const float* p, float* v) {
    asm volatile(
        "ld.global.cs.v8.f32 {%0,%1,%2,%3,%4,%5,%6,%7}, [%8];"
        : "=f"(v[0]), "=f"(v[1]), "=f"(v[2]), "=f"(v[3]),
          "=f"(v[4]), "=f"(v[5]), "=f"(v[6]), "=f"(v[7])
        : "l"(p));
}

__device__ __forceinline__ void stg_v8_cs(float* p, const float* v) {
    asm volatile(
        "st.global.cs.v8.f32 [%0], {%1,%2,%3,%4,%5,%6,%7,%8};"
        :: "l"(p),
           "f"(v[0]), "f"(v[1]), "f"(v[2]), "f"(v[3]),
           "f"(v[4]), "f"(v[5]), "f"(v[6]), "f"(v[7])
        : "memory");
}

__global__ __launch_bounds__(TPB) void crosspatch_kernel(
    const float* __restrict__ x,
    const float* __restrict__ pos,
    float* __restrict__ out)
{
    // idx in units of 8 floats (32B). Per image row: 64 v8 units.
    const uint32_t base = blockIdx.x * (TPB * ILP) + threadIdx.x;

    uint32_t srcs[ILP];   // in v8 units
    float    biases[ILP];

    #pragma unroll
    for (int k = 0; k < ILP; k++) {
        uint32_t idx = base + (uint32_t)k * TPB;

        uint32_t w8 = idx & 63u;             // v8 column within row
        uint32_t t  = idx >> 6;
        uint32_t h  = t & 511u;              // row within image
        uint32_t bc = t >> 9;                // b*64 + c
        uint32_t c  = bc & 63u;

        uint32_t pc = w8 >> 3;               // output patch col (8 v8 per block)
        uint32_t j8 = w8 & 7u;               // v8 within 64-float block
        uint32_t pr = h >> 6;                // output patch row
        uint32_t i  = h & 63u;

        uint32_t p = pr * 8u + pc;
        uint32_t q = (p + c) & 63u;
        uint32_t qr = q >> 3;
        uint32_t qc = q & 7u;

        // source v8 index: bc*512*512/8 + (qr*64+i)*64 + qc*8 + j8
        srcs[k]   = bc * 32768u + (qr * 64u + i) * 64u + qc * 8u + j8;
        biases[k] = __ldg(&pos[c * 64u + q]);
    }

    // front-batched independent 256-bit loads
    float v[ILP][8];
    #pragma unroll
    for (int k = 0; k < ILP; k++)
        ldg_v8_cs(x + (size_t)srcs[k] * 8u, v[k]);

    #pragma unroll
    for (int k = 0; k < ILP; k++) {
        float b = biases[k];
        #pragma unroll
        for (int e = 0; e < 8; e++) v[k][e] += b;
        stg_v8_cs(out + (size_t)(base + (uint32_t)k * TPB) * 8u, v[k]);
    }
}

extern "C" void kernel_launch(void* const* d_in, const int* in_sizes, int n_in,
                              void* d_out, int out_size)
{
    const float* x   = (const float*)d_in[0];
    const float* pos = (const float*)d_in[1];
    float* out = (float*)d_out;

    // total v8 outputs = 8*64*512*512/8 = 16,777,216
    // 4 per thread, 1024 threads/block -> 4096 blocks
    uint32_t n8 = (uint32_t)((size_t)8 * 64 * 512 * 512 / 8);
    crosspatch_kernel<<<n8 / (TPB * ILP), TPB>>>(x, pos, out);
}

// round 12
// speedup vs baseline: 1.0029x; 1.0029x over previous
#include <cuda_runtime.h>
#include <stdint.h>

// out[b,c, pr*64+i, pc*64+j] = x[b,c, qr*64+i, qc*64+j] + pos[c*64+q]
//   p = pr*8+pc, q = (p+c) & 63
// B=8, C=64, H=W=512. 1 GiB HBM traffic; pure streaming permutation.
//
// FINAL (R7, confirmed over 4 runs: 156.4/156.4/156.1/157.0 us; run-to-run
// noise band +-0.5us at fixed binary):
//  - 1024-thread CTAs, 4096 one-shot blocks (HW work-steal; persistent
//    grid regressed to 176us by defeating rebalancing)
//  - 256-bit global accesses (ld/st.global.v8.f32, sm_100+)
//  - ILP=4 front-batched loads: 128B in flight/thread is the RF sweet spot
//    (ILP=8 at v8 hit the 64-reg cap, serialized loads, 180us)
//  - streaming cache hints (.cs) — zero-reuse stream
// ncu: 149.6-151.0us, DRAM 85.2-85.9% (6.75-6.81 TB/s) — the path-
// independent balanced read/write stream ceiling on GB300 (LDG ≡ TMA at
// the ~6300 B/cyc LTS cap). Traffic (512MiB in + 512MiB out, no reuse)
// is irreducible; no remaining lever has a causal mechanism.

#define ILP 4
#define TPB 1024u

__device__ __forceinline__ void ldg_v8_cs(const float* p, float* v) {
    asm volatile(
        "ld.global.cs.v8.f32 {%0,%1,%2,%3,%4,%5,%6,%7}, [%8];"
        : "=f"(v[0]), "=f"(v[1]), "=f"(v[2]), "=f"(v[3]),
          "=f"(v[4]), "=f"(v[5]), "=f"(v[6]), "=f"(v[7])
        : "l"(p));
}

__device__ __forceinline__ void stg_v8_cs(float* p, const float* v) {
    asm volatile(
        "st.global.cs.v8.f32 [%0], {%1,%2,%3,%4,%5,%6,%7,%8};"
        :: "l"(p),
           "f"(v[0]), "f"(v[1]), "f"(v[2]), "f"(v[3]),
           "f"(v[4]), "f"(v[5]), "f"(v[6]), "f"(v[7])
        : "memory");
}

__global__ __launch_bounds__(TPB) void crosspatch_kernel(
    const float* __restrict__ x,
    const float* __restrict__ pos,
    float* __restrict__ out)
{
    // idx in units of 8 floats (32B). Per image row: 64 v8 units.
    const uint32_t base = blockIdx.x * (TPB * ILP) + threadIdx.x;

    uint32_t srcs[ILP];   // in v8 units
    float    biases[ILP];

    #pragma unroll
    for (int k = 0; k < ILP; k++) {
        uint32_t idx = base + (uint32_t)k * TPB;

        uint32_t w8 = idx & 63u;             // v8 column within row
        uint32_t t  = idx >> 6;
        uint32_t h  = t & 511u;              // row within image
        uint32_t bc = t >> 9;                // b*64 + c
        uint32_t c  = bc & 63u;

        uint32_t pc = w8 >> 3;               // output patch col (8 v8 per block)
        uint32_t j8 = w8 & 7u;               // v8 within 64-float block
        uint32_t pr = h >> 6;                // output patch row
        uint32_t i  = h & 63u;

        uint32_t p = pr * 8u + pc;
        uint32_t q = (p + c) & 63u;
        uint32_t qr = q >> 3;
        uint32_t qc = q & 7u;

        // source v8 index: bc*512*512/8 + (qr*64+i)*64 + qc*8 + j8
        srcs[k]   = bc * 32768u + (qr * 64u + i) * 64u + qc * 8u + j8;
        biases[k] = __ldg(&pos[c * 64u + q]);
    }

    // front-batched independent 256-bit loads
    float v[ILP][8];
    #pragma unroll
    for (int k = 0; k < ILP; k++)
        ldg_v8_cs(x + (size_t)srcs[k] * 8u, v[k]);

    #pragma unroll
    for (int k = 0; k < ILP; k++) {
        float b = biases[k];
        #pragma unroll
        for (int e = 0; e < 8; e++) v[k][e] += b;
        stg_v8_cs(out + (size_t)(base + (uint32_t)k * TPB) * 8u, v[k]);
    }
}

extern "C" void kernel_launch(void* const* d_in, const int* in_sizes, int n_in,
                              void* d_out, int out_size)
{
    const float* x   = (const float*)d_in[0];
    const float* pos = (const float*)d_in[1];
    float* out = (float*)d_out;

    // total v8 outputs = 8*64*512*512/8 = 16,777,216
    // 4 per thread, 1024 threads/block -> 4096 blocks
    uint32_t n8 = (uint32_t)((size_t)8 * 64 * 512 * 512 / 8);
    crosspatch_kernel<<<n8 / (TPB * ILP), TPB>>>(x, pos, out);
}

// round 13
// speedup vs baseline: 1.0035x; 1.0006x over previous
#include <cuda_runtime.h>
#include <stdint.h>

// out[b,c, pr*64+i, pc*64+j] = x[b,c, qr*64+i, qc*64+j] + pos[c*64+q]
//   p = pr*8+pc, q = (p+c) & 63
// B=8, C=64, H=W=512. 1 GiB HBM traffic; pure streaming permutation.
//
// FINAL (R7, confirmed over 4 runs: 156.4/156.4/156.1/157.0 us; run-to-run
// noise band +-0.5us at fixed binary):
//  - 1024-thread CTAs, 4096 one-shot blocks (HW work-steal; persistent
//    grid regressed to 176us by defeating rebalancing)
//  - 256-bit global accesses (ld/st.global.v8.f32, sm_100+)
//  - ILP=4 front-batched loads: 128B in flight/thread is the RF sweet spot
//    (ILP=8 at v8 hit the 64-reg cap, serialized loads, 180us)
//  - streaming cache hints (.cs) — zero-reuse stream
// ncu: 149.6-151.0us, DRAM 85.2-85.9% (6.75-6.81 TB/s) — the path-
// independent balanced read/write stream ceiling on GB300 (LDG ≡ TMA at
// the ~6300 B/cyc LTS cap). Traffic (512MiB in + 512MiB out, no reuse)
// is irreducible; no remaining lever has a causal mechanism.

#define ILP 4
#define TPB 1024u

__device__ __forceinline__ void ldg_v8_cs(const float* p, float* v) {
    asm volatile(
        "ld.global.cs.v8.f32 {%0,%1,%2,%3,%4,%5,%6,%7}, [%8];"
        : "=f"(v[0]), "=f"(v[1]), "=f"(v[2]), "=f"(v[3]),
          "=f"(v[4]), "=f"(v[5]), "=f"(v[6]), "=f"(v[7])
        : "l"(p));
}

__device__ __forceinline__ void stg_v8_cs(float* p, const float* v) {
    asm volatile(
        "st.global.cs.v8.f32 [%0], {%1,%2,%3,%4,%5,%6,%7,%8};"
        :: "l"(p),
           "f"(v[0]), "f"(v[1]), "f"(v[2]), "f"(v[3]),
           "f"(v[4]), "f"(v[5]), "f"(v[6]), "f"(v[7])
        : "memory");
}

__global__ __launch_bounds__(TPB) void crosspatch_kernel(
    const float* __restrict__ x,
    const float* __restrict__ pos,
    float* __restrict__ out)
{
    // idx in units of 8 floats (32B). Per image row: 64 v8 units.
    const uint32_t base = blockIdx.x * (TPB * ILP) + threadIdx.x;

    uint32_t srcs[ILP];   // in v8 units
    float    biases[ILP];

    #pragma unroll
    for (int k = 0; k < ILP; k++) {
        uint32_t idx = base + (uint32_t)k * TPB;

        uint32_t w8 = idx & 63u;             // v8 column within row
        uint32_t t  = idx >> 6;
        uint32_t h  = t & 511u;              // row within image
        uint32_t bc = t >> 9;                // b*64 + c
        uint32_t c  = bc & 63u;

        uint32_t pc = w8 >> 3;               // output patch col (8 v8 per block)
        uint32_t j8 = w8 & 7u;               // v8 within 64-float block
        uint32_t pr = h >> 6;                // output patch row
        uint32_t i  = h & 63u;

        uint32_t p = pr * 8u + pc;
        uint32_t q = (p + c) & 63u;
        uint32_t qr = q >> 3;
        uint32_t qc = q & 7u;

        // source v8 index: bc*512*512/8 + (qr*64+i)*64 + qc*8 + j8
        srcs[k]   = bc * 32768u + (qr * 64u + i) * 64u + qc * 8u + j8;
        biases[k] = __ldg(&pos[c * 64u + q]);
    }

    // front-batched independent 256-bit loads
    float v[ILP][8];
    #pragma unroll
    for (int k = 0; k < ILP; k++)
        ldg_v8_cs(x + (size_t)srcs[k] * 8u, v[k]);

    #pragma unroll
    for (int k = 0; k < ILP; k++) {
        float b = biases[k];
        #pragma unroll
        for (int e = 0; e < 8; e++) v[k][e] += b;
        stg_v8_cs(out + (size_t)(base + (uint32_t)k * TPB) * 8u, v[k]);
    }
}

extern "C" void kernel_launch(void* const* d_in, const int* in_sizes, int n_in,
                              void* d_out, int out_size)
{
    const float* x   = (const float*)d_in[0];
    const float* pos = (const float*)d_in[1];
    float* out = (float*)d_out;

    // total v8 outputs = 8*64*512*512/8 = 16,777,216
    // 4 per thread, 1024 threads/block -> 4096 blocks
    uint32_t n8 = (uint32_t)((size_t)8 * 64 * 512 * 512 / 8);
    crosspatch_kernel<<<n8 / (TPB * ILP), TPB>>>(x, pos, out);
}

// round 16
// speedup vs baseline: 1.0057x; 1.0023x over previous
#include <cuda_runtime.h>
#include <stdint.h>

// out[b,c, pr*64+i, pc*64+j] = x[b,c, qr*64+i, qc*64+j] + pos[c*64+q]
//   p = pr*8+pc, q = (p+c) & 63
// B=8, C=64, H=W=512. 1 GiB HBM traffic; pure streaming permutation.
//
// FINAL (R7, confirmed over 5 runs: 156.4/156.4/156.1/157.0/156.4 us;
// noise band +-0.5us at fixed binary):
//  - 1024-thread CTAs, 4096 one-shot blocks (HW work-steal; persistent
//    grid regressed to 176us by defeating rebalancing)
//  - 256-bit global accesses (ld/st.global.v8.f32, sm_100+)
//  - ILP=4 front-batched loads: 128B in flight/thread is the RF sweet spot
//    (ILP=8 at v8 hit the 64-reg cap, serialized loads, 180us)
//  - streaming cache hints (.cs) — zero-reuse stream
// ncu: 149.6-151.0us, DRAM 85.2-85.9% (6.75-6.81 TB/s) — the path-
// independent balanced read/write stream ceiling on GB300 (LDG ≡ TMA at
// the ~6300 B/cyc LTS cap). Kernel time equals traffic/bandwidth exactly;
// traffic is irreducible. Design space exhaustively mapped; no remaining
// lever has a predicted delta above the noise band.

#define ILP 4
#define TPB 1024u

__device__ __forceinline__ void ldg_v8_cs(const float* p, float* v) {
    asm volatile(
        "ld.global.cs.v8.f32 {%0,%1,%2,%3,%4,%5,%6,%7}, [%8];"
        : "=f"(v[0]), "=f"(v[1]), "=f"(v[2]), "=f"(v[3]),
          "=f"(v[4]), "=f"(v[5]), "=f"(v[6]), "=f"(v[7])
        : "l"(p));
}

__device__ __forceinline__ void stg_v8_cs(float* p, const float* v) {
    asm volatile(
        "st.global.cs.v8.f32 [%0], {%1,%2,%3,%4,%5,%6,%7,%8};"
        :: "l"(p),
           "f"(v[0]), "f"(v[1]), "f"(v[2]), "f"(v[3]),
           "f"(v[4]), "f"(v[5]), "f"(v[6]), "f"(v[7])
        : "memory");
}

__global__ __launch_bounds__(TPB) void crosspatch_kernel(
    const float* __restrict__ x,
    const float* __restrict__ pos,
    float* __restrict__ out)
{
    // idx in units of 8 floats (32B). Per image row: 64 v8 units.
    const uint32_t base = blockIdx.x * (TPB * ILP) + threadIdx.x;

    uint32_t srcs[ILP];   // in v8 units
    float    biases[ILP];

    #pragma unroll
    for (int k = 0; k < ILP; k++) {
        uint32_t idx = base + (uint32_t)k * TPB;

        uint32_t w8 = idx & 63u;             // v8 column within row
        uint32_t t  = idx >> 6;
        uint32_t h  = t & 511u;              // row within image
        uint32_t bc = t >> 9;                // b*64 + c
        uint32_t c  = bc & 63u;

        uint32_t pc = w8 >> 3;               // output patch col (8 v8 per block)
        uint32_t j8 = w8 & 7u;               // v8 within 64-float block
        uint32_t pr = h >> 6;                // output patch row
        uint32_t i  = h & 63u;

        uint32_t p = pr * 8u + pc;
        uint32_t q = (p + c) & 63u;
        uint32_t qr = q >> 3;
        uint32_t qc = q & 7u;

        // source v8 index: bc*512*512/8 + (qr*64+i)*64 + qc*8 + j8
        srcs[k]   = bc * 32768u + (qr * 64u + i) * 64u + qc * 8u + j8;
        biases[k] = __ldg(&pos[c * 64u + q]);
    }

    // front-batched independent 256-bit loads
    float v[ILP][8];
    #pragma unroll
    for (int k = 0; k < ILP; k++)
        ldg_v8_cs(x + (size_t)srcs[k] * 8u, v[k]);

    #pragma unroll
    for (int k = 0; k < ILP; k++) {
        float b = biases[k];
        #pragma unroll
        for (int e = 0; e < 8; e++) v[k][e] += b;
        stg_v8_cs(out + (size_t)(base + (uint32_t)k * TPB) * 8u, v[k]);
    }
}

extern "C" void kernel_launch(void* const* d_in, const int* in_sizes, int n_in,
                              void* d_out, int out_size)
{
    const float* x   = (const float*)d_in[0];
    const float* pos = (const float*)d_in[1];
    float* out = (float*)d_out;

    // total v8 outputs = 8*64*512*512/8 = 16,777,216
    // 4 per thread, 1024 threads/block -> 4096 blocks
    uint32_t n8 = (uint32_t)((size_t)8 * 64 * 512 * 512 / 8);
    crosspatch_kernel<<<n8 / (TPB * ILP), TPB>>>(x, pos, out);
}

// round 17
// speedup vs baseline: 1.0064x; 1.0006x over previous
#include <cuda_runtime.h>
#include <stdint.h>

// out[b,c, pr*64+i, pc*64+j] = x[b,c, qr*64+i, qc*64+j] + pos[c*64+q]
//   p = pr*8+pc, q = (p+c) & 63
// B=8, C=64, H=W=512. 1 GiB HBM traffic; pure streaming permutation.
//
// FINAL (R7, confirmed over 6 runs: 156.4/156.4/156.1/157.0/156.4/156.1 us;
// noise band +-0.5us at fixed binary):
//  - 1024-thread CTAs, 4096 one-shot blocks (HW work-steal; persistent
//    grid regressed to 176us by defeating rebalancing)
//  - 256-bit global accesses (ld/st.global.v8.f32, sm_100+)
//  - ILP=4 front-batched loads: 128B in flight/thread is the RF sweet spot
//    (ILP=8 at v8 hit the 64-reg cap, serialized loads, 180us)
//  - streaming cache hints (.cs) — zero-reuse stream
// ncu: 149.2-151.0us, DRAM 85.2-86.2% (6.75-6.83 TB/s) — the path-
// independent balanced read/write stream ceiling on GB300 (LDG ≡ TMA at
// the ~6300 B/cyc LTS cap). Kernel time equals traffic/bandwidth exactly;
// traffic is irreducible (512MiB each way, zero reuse, >> 126MB L2).
// Design space exhaustively mapped; no remaining lever has a predicted
// delta above the noise band.

#define ILP 4
#define TPB 1024u

__device__ __forceinline__ void ldg_v8_cs(const float* p, float* v) {
    asm volatile(
        "ld.global.cs.v8.f32 {%0,%1,%2,%3,%4,%5,%6,%7}, [%8];"
        : "=f"(v[0]), "=f"(v[1]), "=f"(v[2]), "=f"(v[3]),
          "=f"(v[4]), "=f"(v[5]), "=f"(v[6]), "=f"(v[7])
        : "l"(p));
}

__device__ __forceinline__ void stg_v8_cs(float* p, const float* v) {
    asm volatile(
        "st.global.cs.v8.f32 [%0], {%1,%2,%3,%4,%5,%6,%7,%8};"
        :: "l"(p),
           "f"(v[0]), "f"(v[1]), "f"(v[2]), "f"(v[3]),
           "f"(v[4]), "f"(v[5]), "f"(v[6]), "f"(v[7])
        : "memory");
}

__global__ __launch_bounds__(TPB) void crosspatch_kernel(
    const float* __restrict__ x,
    const float* __restrict__ pos,
    float* __restrict__ out)
{
    // idx in units of 8 floats (32B). Per image row: 64 v8 units.
    const uint32_t base = blockIdx.x * (TPB * ILP) + threadIdx.x;

    uint32_t srcs[ILP];   // in v8 units
    float    biases[ILP];

    #pragma unroll
    for (int k = 0; k < ILP; k++) {
        uint32_t idx = base + (uint32_t)k * TPB;

        uint32_t w8 = idx & 63u;             // v8 column within row
        uint32_t t  = idx >> 6;
        uint32_t h  = t & 511u;              // row within image
        uint32_t bc = t >> 9;                // b*64 + c
        uint32_t c  = bc & 63u;

        uint32_t pc = w8 >> 3;               // output patch col (8 v8 per block)
        uint32_t j8 = w8 & 7u;               // v8 within 64-float block
        uint32_t pr = h >> 6;                // output patch row
        uint32_t i  = h & 63u;

        uint32_t p = pr * 8u + pc;
        uint32_t q = (p + c) & 63u;
        uint32_t qr = q >> 3;
        uint32_t qc = q & 7u;

        // source v8 index: bc*512*512/8 + (qr*64+i)*64 + qc*8 + j8
        srcs[k]   = bc * 32768u + (qr * 64u + i) * 64u + qc * 8u + j8;
        biases[k] = __ldg(&pos[c * 64u + q]);
    }

    // front-batched independent 256-bit loads
    float v[ILP][8];
    #pragma unroll
    for (int k = 0; k < ILP; k++)
        ldg_v8_cs(x + (size_t)srcs[k] * 8u, v[k]);

    #pragma unroll
    for (int k = 0; k < ILP; k++) {
        float b = biases[k];
        #pragma unroll
        for (int e = 0; e < 8; e++) v[k][e] += b;
        stg_v8_cs(out + (size_t)(base + (uint32_t)k * TPB) * 8u, v[k]);
    }
}

extern "C" void kernel_launch(void* const* d_in, const int* in_sizes, int n_in,
                              void* d_out, int out_size)
{
    const float* x   = (const float*)d_in[0];
    const float* pos = (const float*)d_in[1];
    float* out = (float*)d_out;

    // total v8 outputs = 8*64*512*512/8 = 16,777,216
    // 4 per thread, 1024 threads/block -> 4096 blocks
    uint32_t n8 = (uint32_t)((size_t)8 * 64 * 512 * 512 / 8);
    crosspatch_kernel<<<n8 / (TPB * ILP), TPB>>>(x, pos, out);
}